// round 14
// baseline (speedup 1.0000x reference)
#include <cuda_runtime.h>
#include <cuda_fp16.h>
#include <math.h>
#include <stdint.h>

// Shapes (fixed)
#define BB   64
#define LQ   32
#define LD   256
#define DD   128
#define NN   2

// ---------------- scratch (no allocation allowed) ----------------
__device__ __align__(16) __half g_qh[BB * LQ * DD];          // normalized q, fp16
__device__ float g_inv[NN * BB * DD];                        // inverse norms over Ld
__device__ float g_S[NN * BB * BB];                          // S[n,bq,bd]
__device__ unsigned int g_done = 0;                          // last-CTA counter

__device__ __forceinline__ uint32_t smem_u32(const void* p) {
    uint32_t a;
    asm("{ .reg .u64 t; cvta.to.shared.u64 t, %1; cvt.u32.u64 %0, t; }" : "=r"(a) : "l"(p));
    return a;
}

__device__ __forceinline__ void ldsm_x4(uint32_t addr, uint32_t& r0, uint32_t& r1,
                                        uint32_t& r2, uint32_t& r3) {
    asm volatile("ldmatrix.sync.aligned.m8n8.x4.shared.b16 {%0,%1,%2,%3}, [%4];"
                 : "=r"(r0), "=r"(r1), "=r"(r2), "=r"(r3) : "r"(addr));
}

__device__ __forceinline__ void lds128(uint32_t addr, uint4& v) {
    asm volatile("ld.shared.v4.b32 {%0,%1,%2,%3}, [%4];"
                 : "=r"(v.x), "=r"(v.y), "=r"(v.z), "=r"(v.w) : "r"(addr));
}

// fp16 inputs, fp32 accumulators
__device__ __forceinline__ void mma_f16_f32(float& c0, float& c1, float& c2, float& c3,
                                            uint32_t a0, uint32_t a1, uint32_t a2, uint32_t a3,
                                            uint32_t b0, uint32_t b1) {
    asm volatile(
        "mma.sync.aligned.m16n8k16.row.col.f32.f16.f16.f32 "
        "{%0,%1,%2,%3}, {%4,%5,%6,%7}, {%8,%9}, {%0,%1,%2,%3};"
        : "+f"(c0), "+f"(c1), "+f"(c2), "+f"(c3)
        : "r"(a0), "r"(a1), "r"(a2), "r"(a3), "r"(b0), "r"(b1));
}

// ---------------------------------------------------------------------------
// Prep kernel: blocks 0..31 -> qnorm (fp16); blocks 32..159 -> dinv.
// ---------------------------------------------------------------------------
__global__ void __launch_bounds__(512)
prep_kernel(const float* __restrict__ q, const float* __restrict__ d,
            const int* __restrict__ mask) {
    if (blockIdx.x < 32) {
        int warp = threadIdx.x >> 5;
        int lane = threadIdx.x & 31;
        #pragma unroll
        for (int r = 0; r < 4; r++) {
            int row = blockIdx.x * 64 + warp * 4 + r;
            const float4* src = (const float4*)(q + (size_t)row * DD);
            float4 v = src[lane];
            float ss = v.x * v.x + v.y * v.y + v.z * v.z + v.w * v.w;
            #pragma unroll
            for (int o = 16; o; o >>= 1) ss += __shfl_xor_sync(0xffffffffu, ss, o);
            float inv = 1.0f / fmaxf(sqrtf(ss), 1e-12f);
            __half2 lo = __float22half2_rn(make_float2(v.x * inv, v.y * inv));
            __half2 hi = __float22half2_rn(make_float2(v.z * inv, v.w * inv));
            uint2 pk;
            pk.x = *(uint32_t*)&lo;
            pk.y = *(uint32_t*)&hi;
            ((uint2*)(g_qh + (size_t)row * DD))[lane] = pk;
        }
    } else {
        __shared__ float part[4][DD];
        int blk = blockIdx.x - 32;
        int dd  = threadIdx.x & 127;
        int seg = threadIdx.x >> 7;
        const float* base = d + (size_t)blk * LD * DD;
        const int*   mb   = mask + (size_t)blk * LD;
        float acc = 0.0f;
        for (int m = seg * 64; m < seg * 64 + 64; m++) {
            float x = base[(size_t)m * DD + dd] * (float)mb[m];
            acc += x * x;
        }
        part[seg][dd] = acc;
        __syncthreads();
        if (seg == 0) {
            float tot = part[0][dd] + part[1][dd] + part[2][dd] + part[3][dd];
            g_inv[(size_t)blk * DD + dd] = 1.0f / fmaxf(sqrtf(tot), 1e-12f);
        }
    }
}

// ---------------------------------------------------------------------------
// Hybrid MaxSim + fused finalize. One CTA per (n,bd), 512 threads.
// Warps 0-11: MMA over cols 0-191 (nc = wid%6, mh = wid/6; 3 warps/SMSP).
// Warps 12-15: SIMT HFMA2 over cols 192-255 (one warp per SMSP).
// Both consume the same fp16 A double-buffer + fp16 B tile.
// ---------------------------------------------------------------------------
#define ABUF_BYTES (256 * 256)                  // 64 KB per A buffer
#define SMEM_TOTAL (2 * ABUF_BYTES + 256 * 256) // 192 KB dynamic

__global__ void __launch_bounds__(512, 1)
maxsim_kernel(const float* __restrict__ d_reps, const int* __restrict__ d_masks,
              const float* __restrict__ labels, float* __restrict__ out) {
    extern __shared__ char smem[];
    const uint32_t Ab0 = smem_u32(smem);
    const uint32_t Bb  = Ab0 + 2 * ABUF_BYTES;
    __shared__ float pm[2][256][8];     // row-max slots: 0-5 MMA, 6-7 SIMT
    __shared__ float s_loss[64];
    __shared__ unsigned s_islast;

    const int tid  = threadIdx.x;
    const int wid  = tid >> 5;
    const int lane = tid & 31;
    const int blk  = blockIdx.x;        // n*B + bd
    const int n    = blk >> 6;
    const int bd   = blk & 63;

    // ---- prefetch A chunk 0 ----
    {
        const uint4* qsrc = (const uint4*)g_qh;
        #pragma unroll 2
        for (int f = tid; f < 256 * 16; f += 512) {
            int row = f >> 4, c = f & 15;
            uint32_t saddr = Ab0 + row * 256 + ((c ^ (row & 7)) * 16);
            asm volatile("cp.async.cg.shared.global [%0], [%1], 16;"
                         :: "r"(saddr), "l"(qsrc + f) : "memory");
        }
        asm volatile("cp.async.commit_group;" ::: "memory");
    }

    // ---- build B tile (mask + seq-normalize + fp16, swizzled) ----
    {
        const float4* dsrc = (const float4*)(d_reps + (size_t)blk * LD * DD);
        const int*    mrow = d_masks + (size_t)blk * LD;
        const float4* inv4 = (const float4*)(g_inv + (size_t)blk * DD);
        for (int f = tid; f < 256 * 16; f += 512) {
            int row = f >> 4, c = f & 15;
            float4 v0 = dsrc[row * 32 + c * 2];
            float4 v1 = dsrc[row * 32 + c * 2 + 1];
            float  mk = (float)mrow[row];
            float4 i0 = inv4[c * 2], i1 = inv4[c * 2 + 1];
            v0.x *= mk * i0.x; v0.y *= mk * i0.y; v0.z *= mk * i0.z; v0.w *= mk * i0.w;
            v1.x *= mk * i1.x; v1.y *= mk * i1.y; v1.z *= mk * i1.z; v1.w *= mk * i1.w;
            __half2 p0 = __float22half2_rn(make_float2(v0.x, v0.y));
            __half2 p1 = __float22half2_rn(make_float2(v0.z, v0.w));
            __half2 p2 = __float22half2_rn(make_float2(v1.x, v1.y));
            __half2 p3 = __float22half2_rn(make_float2(v1.z, v1.w));
            uint32_t addr = Bb + row * 256 + (c ^ (row & 7)) * 16;
            asm volatile("st.shared.v4.b32 [%0], {%1,%2,%3,%4};"
                         :: "r"(addr), "r"(*(uint32_t*)&p0), "r"(*(uint32_t*)&p1),
                            "r"(*(uint32_t*)&p2), "r"(*(uint32_t*)&p3) : "memory");
        }
    }
    __syncthreads();

    // ---- MMA warps: B fragments into registers (once): 32 cols x K=128 ----
    const int nrow_l = (lane & 7) + ((lane >> 3) & 1) * 8;
    const int coff   = lane >> 4;
    const int nc     = wid % 6;         // valid for wid < 12
    const int mh     = wid / 6;
    uint32_t b[8][2][4];
    if (wid < 12) {
        #pragma unroll
        for (int ks = 0; ks < 8; ++ks) {
            #pragma unroll
            for (int np = 0; np < 2; ++np) {
                int nrow = nc * 32 + np * 16 + nrow_l;
                int c = 2 * ks + coff;
                ldsm_x4(Bb + nrow * 256 + ((c ^ (nrow & 7)) * 16),
                        b[ks][np][0], b[ks][np][1], b[ks][np][2], b[ks][np][3]);
            }
        }
    }

    const __half2 h2z = __float2half2_rn(0.0f);

    // ---- 8 chunks of 256 q rows ----
    for (int ch = 0; ch < 8; ++ch) {
        if (ch + 1 < 8) {
            const uint4* qsrc = (const uint4*)(g_qh + (size_t)(ch + 1) * 256 * DD);
            uint32_t Abn = Ab0 + ((ch + 1) & 1) * ABUF_BYTES;
            #pragma unroll 2
            for (int f = tid; f < 256 * 16; f += 512) {
                int row = f >> 4, c = f & 15;
                uint32_t saddr = Abn + row * 256 + ((c ^ (row & 7)) * 16);
                asm volatile("cp.async.cg.shared.global [%0], [%1], 16;"
                             :: "r"(saddr), "l"(qsrc + f) : "memory");
            }
            asm volatile("cp.async.commit_group;" ::: "memory");
            asm volatile("cp.async.wait_group 1;" ::: "memory");
        } else {
            asm volatile("cp.async.wait_group 0;" ::: "memory");
        }
        __syncthreads();    // A(ch) ready; pm[buf] free; A buffer free

        const uint32_t Ab = Ab0 + (ch & 1) * ABUF_BYTES;
        const int buf = ch & 1;

        if (wid < 12) {
            // ---- MMA path: 4 double-tiles over this warp's M-half ----
            #pragma unroll
            for (int mi = 0; mi < 8; mi += 2) {
                const int arow0 = mh * 128 + mi * 16 + (lane & 15);
                const uint32_t rowaddr0 = Ab + arow0 * 256;
                const uint32_t rowaddr1 = rowaddr0 + 16 * 256;
                const uint32_t sw0 = (uint32_t)(arow0 & 7);

                float acc[2][4][4];
                #pragma unroll
                for (int t = 0; t < 2; t++)
                    #pragma unroll
                    for (int jj = 0; jj < 4; jj++)
                        #pragma unroll
                        for (int i = 0; i < 4; i++) acc[t][jj][i] = 0.0f;

                #pragma unroll
                for (int ks = 0; ks < 8; ++ks) {
                    uint32_t a0[4], a1[4];
                    int c = 2 * ks + coff;
                    uint32_t swoff = (uint32_t)((c ^ sw0) * 16);
                    ldsm_x4(rowaddr0 + swoff, a0[0], a0[1], a0[2], a0[3]);
                    ldsm_x4(rowaddr1 + swoff, a1[0], a1[1], a1[2], a1[3]);
                    #pragma unroll
                    for (int np = 0; np < 2; ++np) {
                        mma_f16_f32(acc[0][2*np][0],   acc[0][2*np][1],   acc[0][2*np][2],   acc[0][2*np][3],
                                    a0[0], a0[1], a0[2], a0[3], b[ks][np][0], b[ks][np][2]);
                        mma_f16_f32(acc[1][2*np][0],   acc[1][2*np][1],   acc[1][2*np][2],   acc[1][2*np][3],
                                    a1[0], a1[1], a1[2], a1[3], b[ks][np][0], b[ks][np][2]);
                        mma_f16_f32(acc[0][2*np+1][0], acc[0][2*np+1][1], acc[0][2*np+1][2], acc[0][2*np+1][3],
                                    a0[0], a0[1], a0[2], a0[3], b[ks][np][1], b[ks][np][3]);
                        mma_f16_f32(acc[1][2*np+1][0], acc[1][2*np+1][1], acc[1][2*np+1][2], acc[1][2*np+1][3],
                                    a1[0], a1[1], a1[2], a1[3], b[ks][np][1], b[ks][np][3]);
                    }
                }
                #pragma unroll
                for (int t = 0; t < 2; t++) {
                    float r0 = -INFINITY, r1 = -INFINITY;
                    #pragma unroll
                    for (int jj = 0; jj < 4; jj++) {
                        r0 = fmaxf(r0, fmaxf(acc[t][jj][0], acc[t][jj][1]));
                        r1 = fmaxf(r1, fmaxf(acc[t][jj][2], acc[t][jj][3]));
                    }
                    #pragma unroll
                    for (int o = 1; o <= 2; o <<= 1) {
                        r0 = fmaxf(r0, __shfl_xor_sync(0xffffffffu, r0, o));
                        r1 = fmaxf(r1, __shfl_xor_sync(0xffffffffu, r1, o));
                    }
                    if ((lane & 3) == 0) {
                        int rbase = mh * 128 + (mi + t) * 16 + (lane >> 2);
                        pm[buf][rbase][nc]     = r0;
                        pm[buf][rbase + 8][nc] = r1;
                    }
                }
            }
        } else {
            // ---- SIMT path: cols 192-255 via HFMA2 (fma pipe) ----
            const int sw_ = wid - 12;            // 0..3 (one per SMSP)
            const int rg  = lane >> 2;           // 0..7
            const int cg  = lane & 3;            // 0..3

            #pragma unroll
            for (int rp = 0; rp < 2; ++rp) {
                const int r0 = sw_ * 64 + rg * 8 + rp * 4;   // chunk-local q rows r0..r0+3
                float rmax[4] = {-INFINITY, -INFINITY, -INFINITY, -INFINITY};

                #pragma unroll
                for (int cp = 0; cp < 4; ++cp) {
                    const int c0 = 192 + cg * 16 + cp * 4;   // d cols c0..c0+3
                    __half2 acch[4][4];
                    float   accf[4][4];
                    #pragma unroll
                    for (int rr = 0; rr < 4; rr++)
                        #pragma unroll
                        for (int cc = 0; cc < 4; cc++) { acch[rr][cc] = h2z; accf[rr][cc] = 0.0f; }

                    #pragma unroll
                    for (int s = 0; s < 16; ++s) {           // 8 fp16 per sub-block
                        uint4 qv[4], dv[4];
                        #pragma unroll
                        for (int rr = 0; rr < 4; rr++) {
                            int r = r0 + rr;
                            lds128(Ab + r * 256 + ((s ^ (r & 7)) * 16), qv[rr]);
                        }
                        #pragma unroll
                        for (int cc = 0; cc < 4; cc++) {
                            int c = c0 + cc;
                            lds128(Bb + c * 256 + ((s ^ (c & 7)) * 16), dv[cc]);
                        }
                        #pragma unroll
                        for (int rr = 0; rr < 4; rr++) {
                            const __half2* qh = (const __half2*)&qv[rr];
                            #pragma unroll
                            for (int cc = 0; cc < 4; cc++) {
                                const __half2* dh = (const __half2*)&dv[cc];
                                __half2 a = acch[rr][cc];
                                a = __hfma2(qh[0], dh[0], a);
                                a = __hfma2(qh[1], dh[1], a);
                                a = __hfma2(qh[2], dh[2], a);
                                a = __hfma2(qh[3], dh[3], a);
                                acch[rr][cc] = a;
                            }
                        }
                        if (s == 7) {                         // flush at k=64
                            #pragma unroll
                            for (int rr = 0; rr < 4; rr++)
                                #pragma unroll
                                for (int cc = 0; cc < 4; cc++) {
                                    accf[rr][cc] += __low2float(acch[rr][cc])
                                                  + __high2float(acch[rr][cc]);
                                    acch[rr][cc] = h2z;
                                }
                        }
                    }
                    #pragma unroll
                    for (int rr = 0; rr < 4; rr++)
                        #pragma unroll
                        for (int cc = 0; cc < 4; cc++) {
                            float v = accf[rr][cc] + __low2float(acch[rr][cc])
                                                   + __high2float(acch[rr][cc]);
                            rmax[rr] = fmaxf(rmax[rr], v);
                        }
                }
                // combine cg pairs (0,1) -> slot 6; (2,3) -> slot 7
                #pragma unroll
                for (int rr = 0; rr < 4; rr++)
                    rmax[rr] = fmaxf(rmax[rr], __shfl_xor_sync(0xffffffffu, rmax[rr], 1));
                if ((cg & 1) == 0) {
                    int slot = 6 + (cg >> 1);
                    #pragma unroll
                    for (int rr = 0; rr < 4; rr++)
                        pm[buf][r0 + rr][slot] = rmax[rr];
                }
            }
        }
        __syncthreads();    // pm complete

        // reduce: thread t (<256) -> row t; warp = one bq (32 lq rows)
        if (tid < 256) {
            float4 p0 = *(float4*)&pm[buf][tid][0];
            float4 p1 = *(float4*)&pm[buf][tid][4];
            float v = fmaxf(fmaxf(fmaxf(p0.x, p0.y), fmaxf(p0.z, p0.w)),
                            fmaxf(fmaxf(p1.x, p1.y), fmaxf(p1.z, p1.w)));
            #pragma unroll
            for (int o = 16; o; o >>= 1) v += __shfl_xor_sync(0xffffffffu, v, o);
            if (lane == 0) {
                int bq = ch * 8 + wid;
                g_S[((size_t)n * BB + bq) * BB + bd] = v;
            }
        }
    }

    // ---- last-CTA fused finalize ----
    __syncthreads();
    if (tid == 0) {
        __threadfence();
        s_islast = (atomicAdd(&g_done, 1u) == (unsigned)(gridDim.x - 1));
    }
    __syncthreads();
    if (!s_islast) return;
    __threadfence();

    {
        const int bq = tid >> 3;        // 64 bq x 8 lanes
        const int jj = tid & 7;
        float vmax = -INFINITY;
        #pragma unroll
        for (int nn = 0; nn < NN; nn++)
            #pragma unroll
            for (int k = 0; k < 8; k++)
                vmax = fmaxf(vmax, g_S[((size_t)nn * BB + bq) * BB + (jj + 8 * k)]);
        #pragma unroll
        for (int o = 1; o <= 4; o <<= 1)
            vmax = fmaxf(vmax, __shfl_xor_sync(0xffffffffu, vmax, o));
        float esum = 0.0f;
        #pragma unroll
        for (int nn = 0; nn < NN; nn++)
            #pragma unroll
            for (int k = 0; k < 8; k++)
                esum += expf(g_S[((size_t)nn * BB + bq) * BB + (jj + 8 * k)] - vmax);
        #pragma unroll
        for (int o = 1; o <= 4; o <<= 1)
            esum += __shfl_xor_sync(0xffffffffu, esum, o);

        if (jj == 0) {
            float lse = vmax + logf(esum);
            float s0 = g_S[((size_t)0 * BB + bq) * BB + bq];
            float s1 = g_S[((size_t)1 * BB + bq) * BB + bq];
            float ce_t = lse - s0;
            float m2   = fmaxf(s0, s1);
            float lse2 = m2 + logf(expf(s0 - m2) + expf(s1 - m2));
            float l0 = labels[bq * NN + 0];
            float l1 = labels[bq * NN + 1];
            float kl_t = expf(l0) * (l0 - (s0 - lse2)) + expf(l1) * (l1 - (s1 - lse2));
            s_loss[bq] = kl_t + 0.5f * ce_t;
        }
    }
    __syncthreads();
    if (tid < 64) {
        float v = s_loss[tid];
        #pragma unroll
        for (int o = 16; o; o >>= 1) v += __shfl_xor_sync(0xffffffffu, v, o);
        if (tid == 0)  s_loss[0] = v;
        if (tid == 32) s_loss[1] = v;
    }
    __syncthreads();
    if (tid == 0) {
        out[0] = (s_loss[0] + s_loss[1]) / (float)BB;
        g_done = 0;   // reset for next graph replay
    }
}

// ---------------------------------------------------------------------------
extern "C" void kernel_launch(void* const* d_in, const int* in_sizes, int n_in,
                              void* d_out, int out_size) {
    const float* q_reps  = (const float*)d_in[0];   // [B, Lq, D]
    const float* d_reps  = (const float*)d_in[1];   // [N, B, Ld, D]
    const int*   d_masks = (const int*)d_in[2];     // [N, B, Ld]
    const float* labels  = (const float*)d_in[3];   // [B, N]
    float* out = (float*)d_out;

    prep_kernel<<<160, 512>>>(q_reps, d_reps, d_masks);

    cudaFuncSetAttribute(maxsim_kernel,
                         cudaFuncAttributeMaxDynamicSharedMemorySize, SMEM_TOTAL);
    maxsim_kernel<<<NN * BB, 512, SMEM_TOTAL>>>(d_reps, d_masks, labels, out);
}

// round 16
// speedup vs baseline: 9.0625x; 9.0625x over previous
#include <cuda_runtime.h>
#include <cuda_bf16.h>
#include <math.h>
#include <stdint.h>

// Shapes (fixed)
#define BB   64
#define LQ   32
#define LD   256
#define DD   128
#define NN   2

// ---------------- scratch (no allocation allowed) ----------------
__device__ __align__(16) __nv_bfloat16 g_qbf[BB * LQ * DD];  // normalized q, bf16
__device__ float g_inv[NN * BB * DD];                        // inverse norms over Ld
__device__ float g_S[NN * BB * BB];                          // S[n,bq,bd]
__device__ unsigned int g_done = 0;                          // last-CTA counter

__device__ __forceinline__ uint32_t smem_u32(const void* p) {
    uint32_t a;
    asm("{ .reg .u64 t; cvta.to.shared.u64 t, %1; cvt.u32.u64 %0, t; }" : "=r"(a) : "l"(p));
    return a;
}

__device__ __forceinline__ void ldsm_x4(uint32_t addr, uint32_t& r0, uint32_t& r1,
                                        uint32_t& r2, uint32_t& r3) {
    asm volatile("ldmatrix.sync.aligned.m8n8.x4.shared.b16 {%0,%1,%2,%3}, [%4];"
                 : "=r"(r0), "=r"(r1), "=r"(r2), "=r"(r3) : "r"(addr));
}

__device__ __forceinline__ void mma_bf16(float& c0, float& c1, float& c2, float& c3,
                                         uint32_t a0, uint32_t a1, uint32_t a2, uint32_t a3,
                                         uint32_t b0, uint32_t b1) {
    asm volatile(
        "mma.sync.aligned.m16n8k16.row.col.f32.bf16.bf16.f32 "
        "{%0,%1,%2,%3}, {%4,%5,%6,%7}, {%8,%9}, {%0,%1,%2,%3};"
        : "+f"(c0), "+f"(c1), "+f"(c2), "+f"(c3)
        : "r"(a0), "r"(a1), "r"(a2), "r"(a3), "r"(b0), "r"(b1));
}

// ---------------------------------------------------------------------------
// Prep kernel: blocks 0..31 -> qnorm (bf16); blocks 32..159 -> dinv.
// ---------------------------------------------------------------------------
__global__ void __launch_bounds__(512)
prep_kernel(const float* __restrict__ q, const float* __restrict__ d,
            const int* __restrict__ mask) {
    if (blockIdx.x < 32) {
        int warp = threadIdx.x >> 5;
        int lane = threadIdx.x & 31;
        #pragma unroll
        for (int r = 0; r < 4; r++) {
            int row = blockIdx.x * 64 + warp * 4 + r;
            const float4* src = (const float4*)(q + (size_t)row * DD);
            float4 v = src[lane];
            float ss = v.x * v.x + v.y * v.y + v.z * v.z + v.w * v.w;
            #pragma unroll
            for (int o = 16; o; o >>= 1) ss += __shfl_xor_sync(0xffffffffu, ss, o);
            float inv = 1.0f / fmaxf(sqrtf(ss), 1e-12f);
            __nv_bfloat162 lo = __float22bfloat162_rn(make_float2(v.x * inv, v.y * inv));
            __nv_bfloat162 hi = __float22bfloat162_rn(make_float2(v.z * inv, v.w * inv));
            uint2 pk;
            pk.x = *(uint32_t*)&lo;
            pk.y = *(uint32_t*)&hi;
            ((uint2*)(g_qbf + (size_t)row * DD))[lane] = pk;
        }
    } else {
        __shared__ float part[4][DD];
        int blk = blockIdx.x - 32;
        int dd  = threadIdx.x & 127;
        int seg = threadIdx.x >> 7;
        const float* base = d + (size_t)blk * LD * DD;
        const int*   mb   = mask + (size_t)blk * LD;
        float acc = 0.0f;
        for (int m = seg * 64; m < seg * 64 + 64; m++) {
            float x = base[(size_t)m * DD + dd] * (float)mb[m];
            acc += x * x;
        }
        part[seg][dd] = acc;
        __syncthreads();
        if (seg == 0) {
            float tot = part[0][dd] + part[1][dd] + part[2][dd] + part[3][dd];
            g_inv[(size_t)blk * DD + dd] = 1.0f / fmaxf(sqrtf(tot), 1e-12f);
        }
    }
}

// ---------------------------------------------------------------------------
// MaxSim + fused finalize. One CTA per (n,bd), 512 threads (16 warps).
// warp = 32-col N-chunk (nc = wid&7) x 128-row M-half (mh = wid>>3).
// TWO m16 tiles processed concurrently -> 8 independent accumulator chains
// per warp (doubled RAW distance on the tensor pipe).
// ---------------------------------------------------------------------------
#define ABUF_BYTES (256 * 256)                  // 64 KB per A buffer
#define SMEM_TOTAL (2 * ABUF_BYTES + 256 * 256) // 192 KB dynamic

__global__ void __launch_bounds__(512, 1)
maxsim_kernel(const float* __restrict__ d_reps, const int* __restrict__ d_masks,
              const float* __restrict__ labels, float* __restrict__ out) {
    extern __shared__ char smem[];
    const uint32_t Ab0 = smem_u32(smem);
    const uint32_t Bb  = Ab0 + 2 * ABUF_BYTES;
    __shared__ float pm[2][256][8];     // partial row-max per N-chunk (16 KB)
    __shared__ float s_loss[64];
    __shared__ unsigned s_islast;

    const int tid  = threadIdx.x;
    const int wid  = tid >> 5;
    const int lane = tid & 31;
    const int nc   = wid & 7;           // N-chunk (32 cols)
    const int mh   = wid >> 3;          // M-half (128 rows)
    const int blk  = blockIdx.x;        // n*B + bd
    const int n    = blk >> 6;
    const int bd   = blk & 63;

    // ---- prefetch A chunk 0 ----
    {
        const uint4* qsrc = (const uint4*)g_qbf;
        #pragma unroll 2
        for (int f = tid; f < 256 * 16; f += 512) {
            int row = f >> 4, c = f & 15;
            uint32_t saddr = Ab0 + row * 256 + ((c ^ (row & 7)) * 16);
            asm volatile("cp.async.cg.shared.global [%0], [%1], 16;"
                         :: "r"(saddr), "l"(qsrc + f) : "memory");
        }
        asm volatile("cp.async.commit_group;" ::: "memory");
    }

    // ---- build B tile (mask + seq-normalize + bf16, swizzled) ----
    {
        const float4* dsrc = (const float4*)(d_reps + (size_t)blk * LD * DD);
        const int*    mrow = d_masks + (size_t)blk * LD;
        const float4* inv4 = (const float4*)(g_inv + (size_t)blk * DD);
        for (int f = tid; f < 256 * 16; f += 512) {
            int row = f >> 4, c = f & 15;
            float4 v0 = dsrc[row * 32 + c * 2];
            float4 v1 = dsrc[row * 32 + c * 2 + 1];
            float  mk = (float)mrow[row];
            float4 i0 = inv4[c * 2], i1 = inv4[c * 2 + 1];
            v0.x *= mk * i0.x; v0.y *= mk * i0.y; v0.z *= mk * i0.z; v0.w *= mk * i0.w;
            v1.x *= mk * i1.x; v1.y *= mk * i1.y; v1.z *= mk * i1.z; v1.w *= mk * i1.w;
            __nv_bfloat162 p0 = __float22bfloat162_rn(make_float2(v0.x, v0.y));
            __nv_bfloat162 p1 = __float22bfloat162_rn(make_float2(v0.z, v0.w));
            __nv_bfloat162 p2 = __float22bfloat162_rn(make_float2(v1.x, v1.y));
            __nv_bfloat162 p3 = __float22bfloat162_rn(make_float2(v1.z, v1.w));
            uint32_t addr = Bb + row * 256 + (c ^ (row & 7)) * 16;
            asm volatile("st.shared.v4.b32 [%0], {%1,%2,%3,%4};"
                         :: "r"(addr), "r"(*(uint32_t*)&p0), "r"(*(uint32_t*)&p1),
                            "r"(*(uint32_t*)&p2), "r"(*(uint32_t*)&p3) : "memory");
        }
    }
    __syncthreads();

    // ---- load B fragments into registers (once): 32 cols x K=128 ----
    const int nrow_l = (lane & 7) + ((lane >> 3) & 1) * 8;
    const int coff   = lane >> 4;
    uint32_t b[8][2][4];
    #pragma unroll
    for (int ks = 0; ks < 8; ++ks) {
        #pragma unroll
        for (int np = 0; np < 2; ++np) {
            int nrow = nc * 32 + np * 16 + nrow_l;
            int c = 2 * ks + coff;
            ldsm_x4(Bb + nrow * 256 + ((c ^ (nrow & 7)) * 16),
                    b[ks][np][0], b[ks][np][1], b[ks][np][2], b[ks][np][3]);
        }
    }

    // ---- 8 chunks of 256 q rows ----
    for (int ch = 0; ch < 8; ++ch) {
        if (ch + 1 < 8) {
            const uint4* qsrc = (const uint4*)(g_qbf + (size_t)(ch + 1) * 256 * DD);
            uint32_t Abn = Ab0 + ((ch + 1) & 1) * ABUF_BYTES;
            #pragma unroll 2
            for (int f = tid; f < 256 * 16; f += 512) {
                int row = f >> 4, c = f & 15;
                uint32_t saddr = Abn + row * 256 + ((c ^ (row & 7)) * 16);
                asm volatile("cp.async.cg.shared.global [%0], [%1], 16;"
                             :: "r"(saddr), "l"(qsrc + f) : "memory");
            }
            asm volatile("cp.async.commit_group;" ::: "memory");
            asm volatile("cp.async.wait_group 1;" ::: "memory");
        } else {
            asm volatile("cp.async.wait_group 0;" ::: "memory");
        }
        __syncthreads();    // A(ch) ready; pm[buf] free; A buffer free

        const uint32_t Ab = Ab0 + (ch & 1) * ABUF_BYTES;
        const int buf = ch & 1;

        // ---- 4 double-tiles (2 m16 tiles each) for this warp's M-half ----
        #pragma unroll
        for (int mi = 0; mi < 8; mi += 2) {
            const int arow0 = mh * 128 + mi * 16 + (lane & 15);
            const uint32_t rowaddr0 = Ab + arow0 * 256;
            const uint32_t rowaddr1 = rowaddr0 + 16 * 256;
            const uint32_t sw0 = (uint32_t)(arow0 & 7);   // (arow1 & 7) == sw0

            float acc[2][4][4];                 // 8 independent chains
            #pragma unroll
            for (int t = 0; t < 2; t++)
                #pragma unroll
                for (int jj = 0; jj < 4; jj++)
                    #pragma unroll
                    for (int i = 0; i < 4; i++) acc[t][jj][i] = 0.0f;

            #pragma unroll
            for (int ks = 0; ks < 8; ++ks) {
                uint32_t a0[4], a1[4];
                int c = 2 * ks + coff;
                uint32_t swoff = (uint32_t)((c ^ sw0) * 16);
                ldsm_x4(rowaddr0 + swoff, a0[0], a0[1], a0[2], a0[3]);
                ldsm_x4(rowaddr1 + swoff, a1[0], a1[1], a1[2], a1[3]);
                #pragma unroll
                for (int np = 0; np < 2; ++np) {
                    mma_bf16(acc[0][2*np][0],   acc[0][2*np][1],   acc[0][2*np][2],   acc[0][2*np][3],
                             a0[0], a0[1], a0[2], a0[3], b[ks][np][0], b[ks][np][2]);
                    mma_bf16(acc[1][2*np][0],   acc[1][2*np][1],   acc[1][2*np][2],   acc[1][2*np][3],
                             a1[0], a1[1], a1[2], a1[3], b[ks][np][0], b[ks][np][2]);
                    mma_bf16(acc[0][2*np+1][0], acc[0][2*np+1][1], acc[0][2*np+1][2], acc[0][2*np+1][3],
                             a0[0], a0[1], a0[2], a0[3], b[ks][np][1], b[ks][np][3]);
                    mma_bf16(acc[1][2*np+1][0], acc[1][2*np+1][1], acc[1][2*np+1][2], acc[1][2*np+1][3],
                             a1[0], a1[1], a1[2], a1[3], b[ks][np][1], b[ks][np][3]);
                }
            }

            // row-max over this warp's 32 cols, both tiles
            #pragma unroll
            for (int t = 0; t < 2; t++) {
                float r0 = -INFINITY, r1 = -INFINITY;
                #pragma unroll
                for (int jj = 0; jj < 4; jj++) {
                    r0 = fmaxf(r0, fmaxf(acc[t][jj][0], acc[t][jj][1]));
                    r1 = fmaxf(r1, fmaxf(acc[t][jj][2], acc[t][jj][3]));
                }
                #pragma unroll
                for (int o = 1; o <= 2; o <<= 1) {
                    r0 = fmaxf(r0, __shfl_xor_sync(0xffffffffu, r0, o));
                    r1 = fmaxf(r1, __shfl_xor_sync(0xffffffffu, r1, o));
                }
                if ((lane & 3) == 0) {
                    int rbase = mh * 128 + (mi + t) * 16 + (lane >> 2);
                    pm[buf][rbase][nc]     = r0;
                    pm[buf][rbase + 8][nc] = r1;
                }
            }
        }
        __syncthreads();    // pm complete

        // reduce: thread t (<256) -> row t; warp = one bq (32 lq rows)
        if (tid < 256) {
            float4 p0 = *(float4*)&pm[buf][tid][0];
            float4 p1 = *(float4*)&pm[buf][tid][4];
            float v = fmaxf(fmaxf(fmaxf(p0.x, p0.y), fmaxf(p0.z, p0.w)),
                            fmaxf(fmaxf(p1.x, p1.y), fmaxf(p1.z, p1.w)));
            #pragma unroll
            for (int o = 16; o; o >>= 1) v += __shfl_xor_sync(0xffffffffu, v, o);
            if (lane == 0) {
                int bq = ch * 8 + wid;
                g_S[((size_t)n * BB + bq) * BB + bd] = v;
            }
        }
    }

    // ---- last-CTA fused finalize ----
    __syncthreads();
    if (tid == 0) {
        __threadfence();
        s_islast = (atomicAdd(&g_done, 1u) == (unsigned)(gridDim.x - 1));
    }
    __syncthreads();
    if (!s_islast) return;
    __threadfence();

    {
        const int bq = tid >> 3;        // 64 bq x 8 lanes
        const int jj = tid & 7;
        float vmax = -INFINITY;
        #pragma unroll
        for (int nn = 0; nn < NN; nn++)
            #pragma unroll
            for (int k = 0; k < 8; k++)
                vmax = fmaxf(vmax, g_S[((size_t)nn * BB + bq) * BB + (jj + 8 * k)]);
        #pragma unroll
        for (int o = 1; o <= 4; o <<= 1)
            vmax = fmaxf(vmax, __shfl_xor_sync(0xffffffffu, vmax, o));
        float esum = 0.0f;
        #pragma unroll
        for (int nn = 0; nn < NN; nn++)
            #pragma unroll
            for (int k = 0; k < 8; k++)
                esum += expf(g_S[((size_t)nn * BB + bq) * BB + (jj + 8 * k)] - vmax);
        #pragma unroll
        for (int o = 1; o <= 4; o <<= 1)
            esum += __shfl_xor_sync(0xffffffffu, esum, o);

        if (jj == 0) {
            float lse = vmax + logf(esum);
            float s0 = g_S[((size_t)0 * BB + bq) * BB + bq];
            float s1 = g_S[((size_t)1 * BB + bq) * BB + bq];
            float ce_t = lse - s0;
            float m2   = fmaxf(s0, s1);
            float lse2 = m2 + logf(expf(s0 - m2) + expf(s1 - m2));
            float l0 = labels[bq * NN + 0];
            float l1 = labels[bq * NN + 1];
            float kl_t = expf(l0) * (l0 - (s0 - lse2)) + expf(l1) * (l1 - (s1 - lse2));
            s_loss[bq] = kl_t + 0.5f * ce_t;
        }
    }
    __syncthreads();
    if (tid < 64) {
        float v = s_loss[tid];
        #pragma unroll
        for (int o = 16; o; o >>= 1) v += __shfl_xor_sync(0xffffffffu, v, o);
        if (tid == 0)  s_loss[0] = v;
        if (tid == 32) s_loss[1] = v;
    }
    __syncthreads();
    if (tid == 0) {
        out[0] = (s_loss[0] + s_loss[1]) / (float)BB;
        g_done = 0;   // reset for next graph replay
    }
}

// ---------------------------------------------------------------------------
extern "C" void kernel_launch(void* const* d_in, const int* in_sizes, int n_in,
                              void* d_out, int out_size) {
    const float* q_reps  = (const float*)d_in[0];   // [B, Lq, D]
    const float* d_reps  = (const float*)d_in[1];   // [N, B, Ld, D]
    const int*   d_masks = (const int*)d_in[2];     // [N, B, Ld]
    const float* labels  = (const float*)d_in[3];   // [B, N]
    float* out = (float*)d_out;

    prep_kernel<<<160, 512>>>(q_reps, d_reps, d_masks);

    cudaFuncSetAttribute(maxsim_kernel,
                         cudaFuncAttributeMaxDynamicSharedMemorySize, SMEM_TOTAL);
    maxsim_kernel<<<NN * BB, 512, SMEM_TOTAL>>>(d_reps, d_masks, labels, out);
}